// round 1
// baseline (speedup 1.0000x reference)
#include <cuda_runtime.h>

// Problem constants (fixed by the reference):
//   T=4 tables, N=1,000,000 rows, D=4, B=16384 bags, TOTAL=819,200 lookups/table.
// Inputs (metadata order):
//   d_in[0] tables  f32 [T*N*D]   = 16,000,000
//   d_in[1] W       f32 [1*D]     = 4
//   d_in[2] b       f32 [1]       = 1
//   d_in[3] indices i32 [T*TOTAL] = 3,276,800
//   d_in[4] seg_ids i32 [T*TOTAL] = 3,276,800 (sorted per table)
// Output: f32 [T*B] = 65,536.   out[t*B+s] = b + sum_{seg=s} dot(tables[t,idx], W)

#define EMB_T      4
#define EMB_N      1000000
#define EMB_B      16384
#define EMB_TOTAL  819200

__global__ void init_out_kernel(float* __restrict__ out,
                                const float* __restrict__ b,
                                int n) {
    int i = blockIdx.x * blockDim.x + threadIdx.x;
    if (i < n) out[i] = __ldg(b);
}

__global__ __launch_bounds__(256)
void embbag_pool_kernel(const float4* __restrict__ tables,   // [T*N] float4 rows
                        const float*  __restrict__ W,        // [4]
                        const int*    __restrict__ indices,  // [T*TOTAL]
                        const int*    __restrict__ segs,     // [T*TOTAL]
                        float*        __restrict__ out)      // [T*B]
{
    const int g = blockIdx.x * blockDim.x + threadIdx.x;   // 0 .. T*TOTAL-1
    // TOTAL % 32 == 0  =>  a warp never straddles a table boundary.
    const int t = g / EMB_TOTAL;

    const float w0 = __ldg(W + 0);
    const float w1 = __ldg(W + 1);
    const float w2 = __ldg(W + 2);
    const float w3 = __ldg(W + 3);

    const int idx = __ldg(indices + g);
    const int seg = __ldg(segs + g);

    const float4 r = __ldg(&tables[(size_t)t * EMB_N + (size_t)idx]);
    float v = r.x * w0 + r.y * w1 + r.z * w2 + r.w * w3;

    // Warp-segmented inclusive scan on (seg, v). segs are sorted, so segments
    // are contiguous runs within the warp.
    const unsigned lane = threadIdx.x & 31u;
    #pragma unroll
    for (int off = 1; off < 32; off <<= 1) {
        const float up  = __shfl_up_sync(0xffffffffu, v, off);
        const int   sup = __shfl_up_sync(0xffffffffu, seg, off);
        if (lane >= (unsigned)off && sup == seg) v += up;
    }

    // Lane holds the segment total iff it is the last lane of its run.
    const int next_seg = __shfl_down_sync(0xffffffffu, seg, 1);
    if (lane == 31u || next_seg != seg) {
        atomicAdd(out + t * EMB_B + seg, v);
    }
}

extern "C" void kernel_launch(void* const* d_in, const int* in_sizes, int n_in,
                              void* d_out, int out_size) {
    const float4* tables  = (const float4*)d_in[0];
    const float*  W       = (const float*)d_in[1];
    const float*  b       = (const float*)d_in[2];
    const int*    indices = (const int*)d_in[3];
    const int*    segs    = (const int*)d_in[4];
    float*        out     = (float*)d_out;           // 65,536 floats

    const int n_out = EMB_T * EMB_B;                  // 65,536
    init_out_kernel<<<(n_out + 255) / 256, 256>>>(out, b, n_out);

    const int n_elem = EMB_T * EMB_TOTAL;             // 3,276,800
    embbag_pool_kernel<<<n_elem / 256, 256>>>(tables, W, indices, segs, out);
}

// round 3
// speedup vs baseline: 1.2653x; 1.2653x over previous
#include <cuda_runtime.h>

// T=4 tables, N=1,000,000 rows, D=4, B=16384 bags, TOTAL=819,200 lookups/table.
// out[t*B+s] = b + sum_{i: seg[t,i]=s} dot(tables[t, idx[t,i]], W)
// (Linear(4,1) pushed inside the pooling: dot per gathered row, scalar segment-sum.)

#define EMB_T      4
#define EMB_N      1000000
#define EMB_B      16384
#define EMB_TOTAL  819200

__global__ void init_out_kernel(float* __restrict__ out,
                                const float* __restrict__ b,
                                int n) {
    int i = blockIdx.x * blockDim.x + threadIdx.x;
    if (i < n) out[i] = __ldg(b);
}

// Cache-policy handles (createpolicy form — immediate .L2::evict_* on ld.v4.f32
// is rejected by this ptxas).
__device__ __forceinline__ unsigned long long policy_evict_last() {
    unsigned long long p;
    asm volatile("createpolicy.fractional.L2::evict_last.b64 %0, 1.0;" : "=l"(p));
    return p;
}
__device__ __forceinline__ unsigned long long policy_evict_first() {
    unsigned long long p;
    asm volatile("createpolicy.fractional.L2::evict_first.b64 %0, 1.0;" : "=l"(p));
    return p;
}

// Table row gather: keep in L2 across graph replays.
__device__ __forceinline__ float4 ldg_hot_f4(const float4* p, unsigned long long pol) {
    float4 r;
    asm volatile("ld.global.nc.L2::cache_hint.v4.f32 {%0,%1,%2,%3}, [%4], %5;"
                 : "=f"(r.x), "=f"(r.y), "=f"(r.z), "=f"(r.w) : "l"(p), "l"(pol));
    return r;
}

// Streamed indices/segments: don't pollute L2.
__device__ __forceinline__ int4 ldg_stream_i4(const int4* p, unsigned long long pol) {
    int4 r;
    asm volatile("ld.global.nc.L2::cache_hint.v4.b32 {%0,%1,%2,%3}, [%4], %5;"
                 : "=r"(r.x), "=r"(r.y), "=r"(r.z), "=r"(r.w) : "l"(p), "l"(pol));
    return r;
}

__global__ __launch_bounds__(256)
void embbag_pool4_kernel(const float4* __restrict__ tables,   // [T*N] rows
                         const float*  __restrict__ W,        // [4]
                         const int*    __restrict__ indices,  // [T*TOTAL]
                         const int*    __restrict__ segs,     // [T*TOTAL]
                         float*        __restrict__ out)      // [T*B]
{
    const int g0 = (blockIdx.x * blockDim.x + threadIdx.x) * 4;  // first of 4 elems
    // TOTAL % 128 == 0 => a thread's 4 elements (and a warp's 128) share one table.
    const int t = g0 / EMB_TOTAL;
    const unsigned lane = threadIdx.x & 31u;

    const unsigned long long pol_hot    = policy_evict_last();
    const unsigned long long pol_stream = policy_evict_first();

    const float4 w = __ldg((const float4*)W);

    const int4 idx = ldg_stream_i4((const int4*)(indices + g0), pol_stream);
    const int4 sg  = ldg_stream_i4((const int4*)(segs + g0), pol_stream);

    const float4* tbl = tables + (size_t)t * EMB_N;
    // 4 independent gathers in flight (MLP=4 per thread).
    const float4 r0 = ldg_hot_f4(tbl + idx.x, pol_hot);
    const float4 r1 = ldg_hot_f4(tbl + idx.y, pol_hot);
    const float4 r2 = ldg_hot_f4(tbl + idx.z, pol_hot);
    const float4 r3 = ldg_hot_f4(tbl + idx.w, pol_hot);

    const float v0 = r0.x * w.x + r0.y * w.y + r0.z * w.z + r0.w * w.w;
    const float v1 = r1.x * w.x + r1.y * w.y + r1.z * w.z + r1.w * w.w;
    const float v2 = r2.x * w.x + r2.y * w.y + r2.z * w.z + r2.w * w.w;
    const float v3 = r3.x * w.x + r3.y * w.y + r3.z * w.z + r3.w * w.w;

    float* obase = out + t * EMB_B;

    // ---- intra-thread run decomposition (segments are sorted) ----
    const bool e01 = (sg.x == sg.y);
    const bool e12 = (sg.y == sg.z);
    const bool e23 = (sg.z == sg.w);
    const bool all_same = e01 && e12 && e23;

    // head run (contains element 0), tail run (contains element 3)
    const float head_sum = v0 + (e01 ? (v1 + (e12 ? (v2 + (e23 ? v3 : 0.f)) : 0.f)) : 0.f);
    const float tail_sum = v3 + (e23 ? (v2 + (e12 ? (v1 + (e01 ? v0 : 0.f)) : 0.f)) : 0.f);

    // complete runs strictly inside the 4-window -> flush directly (rare)
    if (!e01 && !e12)           atomicAdd(obase + sg.y, v1);
    if (!e12 && !e23)           atomicAdd(obase + sg.z, v2);
    if (!e01 &&  e12 && !e23)   atomicAdd(obase + sg.y, v1 + v2);

    // ---- warp segmented scan over per-thread tail aggregates ----
    const int prev_s3 = __shfl_up_sync(0xffffffffu, sg.w, 1);
    // lane continues previous lane's run only if this thread is single-segment
    // and its segment matches the previous thread's last segment
    int f = (all_same && lane > 0u && prev_s3 == sg.x) ? 0 : 1;
    float x = tail_sum;
    #pragma unroll
    for (int off = 1; off < 32; off <<= 1) {
        const float xo = __shfl_up_sync(0xffffffffu, x, off);
        const int   fo = __shfl_up_sync(0xffffffffu, f, off);
        if (lane >= (unsigned)off) {
            if (!f) x += xo;
            f |= fo;
        }
    }

    // carry from previous lane's inclusive scan into this thread's head run
    const float x_prev = __shfl_up_sync(0xffffffffu, x, 1);
    if (!all_same) {
        float head_total = head_sum;
        if (lane > 0u && prev_s3 == sg.x) head_total += x_prev;
        atomicAdd(obase + sg.x, head_total);
    }

    // flush tail-inclusive value if the run ends here
    const int next_s0 = __shfl_down_sync(0xffffffffu, sg.x, 1);
    if (lane == 31u || next_s0 != sg.w) {
        atomicAdd(obase + sg.w, x);
    }
}

extern "C" void kernel_launch(void* const* d_in, const int* in_sizes, int n_in,
                              void* d_out, int out_size) {
    const float4* tables  = (const float4*)d_in[0];
    const float*  W       = (const float*)d_in[1];
    const float*  b       = (const float*)d_in[2];
    const int*    indices = (const int*)d_in[3];
    const int*    segs    = (const int*)d_in[4];
    float*        out     = (float*)d_out;

    const int n_out = EMB_T * EMB_B;                       // 65,536
    init_out_kernel<<<(n_out + 255) / 256, 256>>>(out, b, n_out);

    const int n_threads = (EMB_T * EMB_TOTAL) / 4;         // 819,200
    embbag_pool4_kernel<<<n_threads / 256, 256>>>(tables, W, indices, segs, out);
}